// round 14
// baseline (speedup 1.0000x reference)
#include <cuda_runtime.h>
#include <math.h>

#define NN   50000
#define FIN  256
#define H1N  8
#define F1   256
#define NEG  0.2f
#define EMAX 900000
#define FULL 0xffffffffu
#define NB_SCAN ((NN + 1023) / 1024)

// ---------------- scratch ----------------
__device__ __align__(256) float g_h1[NN * F1];
__device__ __align__(256) float g_el1[NN * H1N];
__device__ __align__(256) float g_er1[NN * H1N];
__device__ __align__(256) float g_x1[NN * F1];
__device__ __align__(256) float g_h2res[NN * 128];   // [h2 (64) | residual (64)]
__device__ __align__(256) float g_el2[NN];
__device__ __align__(256) float g_er2[NN];
__device__ __align__(256) float g_Bcat[FIN * 128];
__device__ __align__(256) float g_w1l[FIN * H1N];    // W1 . al1  [256][8]
__device__ __align__(256) float g_w1r[FIN * H1N];    // W1 . ar1
__device__ int g_deg[NN];
__device__ int g_off[NN + 1];
__device__ int g_bsum[64];
__device__ int g_us[EMAX];

// ---------------- CSR build ----------------
__global__ void k_hist(const int* __restrict__ dst, int E, int* __restrict__ deg) {
    int i = blockIdx.x * blockDim.x + threadIdx.x;
    if (i < E) atomicAdd(&deg[dst[i]], 1);
}

__global__ void k_scan_blk(const int* __restrict__ deg, int* __restrict__ off,
                           int* __restrict__ bsum, int n) {
    __shared__ int wsum[32];
    int tid = threadIdx.x, lane = tid & 31, wid = tid >> 5;
    int i = blockIdx.x * 1024 + tid;
    int v = (i < n) ? deg[i] : 0;
    int x = v;
    #pragma unroll
    for (int o = 1; o < 32; o <<= 1) {
        int y = __shfl_up_sync(FULL, x, o);
        if (lane >= o) x += y;
    }
    if (lane == 31) wsum[wid] = x;
    __syncthreads();
    if (wid == 0) {
        int w = wsum[lane];
        #pragma unroll
        for (int o = 1; o < 32; o <<= 1) {
            int y = __shfl_up_sync(FULL, w, o);
            if (lane >= o) w += y;
        }
        wsum[lane] = w;
    }
    __syncthreads();
    int incl = x + (wid ? wsum[wid - 1] : 0);
    if (i < n) off[i] = incl - v;
    if (tid == 1023) bsum[blockIdx.x] = incl;
}

__global__ void k_scan_top(int* __restrict__ bsum, int nb) {
    if (threadIdx.x == 0) {
        int run = 0;
        for (int b = 0; b < nb; b++) {
            int t = bsum[b];
            bsum[b] = run;
            run += t;
        }
    }
}

__global__ void k_scan_add(int* __restrict__ off, const int* __restrict__ bsum,
                           int n, int E) {
    int i = blockIdx.x * 1024 + threadIdx.x;
    if (i < n) off[i] += bsum[blockIdx.x];
    if (i == 0) off[n] = E;
}

__global__ void k_scatter(const int* __restrict__ src, const int* __restrict__ dst,
                          int E, const int* __restrict__ off, int* __restrict__ cur,
                          int* __restrict__ us) {
    int i = blockIdx.x * blockDim.x + threadIdx.x;
    if (i < E) {
        int d = dst[i];
        int p = off[d] + atomicAdd(&cur[d], 1);
        us[p] = src[i];
    }
}

// ---------------- attn-vector precompose: w1l[f][h] = sum_j W1[f][h*32+j]*al[h][j] ----
__global__ void k_prevec(const float* __restrict__ W1, const float* __restrict__ al,
                         const float* __restrict__ ar, float* __restrict__ w1l,
                         float* __restrict__ w1r) {
    int wid = (blockIdx.x * blockDim.x + threadIdx.x) >> 5;   // 0..2047
    if (wid >= FIN * H1N) return;
    int lane = threadIdx.x & 31;
    int f = wid >> 3, h = wid & 7;
    float p = W1[f * F1 + h * 32 + lane];
    float sl = p * al[h * 32 + lane];
    float sr = p * ar[h * 32 + lane];
    #pragma unroll
    for (int o = 16; o; o >>= 1) {
        sl += __shfl_xor_sync(FULL, sl, o);
        sr += __shfl_xor_sync(FULL, sr, o);
    }
    if (lane == 0) {
        w1l[f * 8 + h] = sl;
        w1r[f * 8 + h] = sr;
    }
}

// ---------------- el1/er1 = feats @ w1l / w1r (warp per node; side stream) --------
__global__ __launch_bounds__(256)
void k_attnpre1(const float* __restrict__ feats, const float* __restrict__ w1l,
                const float* __restrict__ w1r, float* __restrict__ el,
                float* __restrict__ er) {
    int w = (blockIdx.x * blockDim.x + threadIdx.x) >> 5;
    if (w >= NN) return;
    int lane = threadIdx.x & 31;
    const float4* fp = (const float4*)(feats + (size_t)w * FIN + lane * 8);
    float4 v0 = fp[0], v1 = fp[1];
    float fv[8] = {v0.x, v0.y, v0.z, v0.w, v1.x, v1.y, v1.z, v1.w};
    float al[8] = {}, ar[8] = {};
    #pragma unroll
    for (int j = 0; j < 8; j++) {
        int f = lane * 8 + j;
        float4 l0 = *(const float4*)&w1l[f * 8];
        float4 l1 = *(const float4*)&w1l[f * 8 + 4];
        float4 r0 = *(const float4*)&w1r[f * 8];
        float4 r1 = *(const float4*)&w1r[f * 8 + 4];
        float x = fv[j];
        al[0] += x * l0.x; al[1] += x * l0.y; al[2] += x * l0.z; al[3] += x * l0.w;
        al[4] += x * l1.x; al[5] += x * l1.y; al[6] += x * l1.z; al[7] += x * l1.w;
        ar[0] += x * r0.x; ar[1] += x * r0.y; ar[2] += x * r0.z; ar[3] += x * r0.w;
        ar[4] += x * r1.x; ar[5] += x * r1.y; ar[6] += x * r1.z; ar[7] += x * r1.w;
    }
    #pragma unroll
    for (int h = 0; h < 8; h++) {
        #pragma unroll
        for (int o = 16; o; o >>= 1) {
            al[h] += __shfl_xor_sync(FULL, al[h], o);
            ar[h] += __shfl_xor_sync(FULL, ar[h], o);
        }
    }
    #pragma unroll
    for (int h = 0; h < 8; h++) {
        if (lane == h) {
            el[w * 8 + h] = al[h];
            er[w * 8 + h] = ar[h];
        }
    }
}

// ---------------- TF32 GEMM: A smem columns permuted for LDS.64 fragment loads ----
// col' = k8*8 + (kk<4 ? 2*kk : 2*(kk-4)+1)  ->  frag pair (q, q+4) adjacent.
__device__ __forceinline__ unsigned f2tf(float x) {
    unsigned u;
    asm("cvt.rna.tf32.f32 %0, %1;" : "=r"(u) : "f"(x));
    return u;
}

__device__ __forceinline__ void mma_tf32(float* d, const unsigned* a, const unsigned* b) {
    asm volatile(
        "mma.sync.aligned.m16n8k8.row.col.f32.tf32.tf32.f32 "
        "{%0,%1,%2,%3}, {%4,%5,%6,%7}, {%8,%9}, {%0,%1,%2,%3};\n"
        : "+f"(d[0]), "+f"(d[1]), "+f"(d[2]), "+f"(d[3])
        : "r"(a[0]), "r"(a[1]), "r"(a[2]), "r"(a[3]), "r"(b[0]), "r"(b[1]));
}

__global__ __launch_bounds__(256)
void k_mma_gemm(const float* __restrict__ A, const float* __restrict__ B,
                float* __restrict__ C, int M, int N, int K) {
    __shared__ unsigned As[128][36];
    __shared__ unsigned Bs[32][72];
    int t = threadIdx.x;
    int lane = t & 31;
    int warp = t >> 5;
    int g = lane >> 2, q = lane & 3;
    int warpM = warp & 3, warpN = warp >> 2;
    int bm = blockIdx.x * 128, bn = blockIdx.y * 64;

    float4 avs[4], bvs[2];
    float acc[2][4][4] = {};

    auto loadA = [&](int kt) {
        #pragma unroll
        for (int i = 0; i < 4; i++) {
            int idx = t + i * 256;
            int r = idx >> 3, c4 = (idx & 7) * 4;
            float4 v = make_float4(0.f, 0.f, 0.f, 0.f);
            if (bm + r < M)
                v = *(const float4*)&A[(size_t)(bm + r) * K + kt + c4];
            avs[i] = v;
        }
    };
    auto loadB = [&](int kt) {
        #pragma unroll
        for (int i = 0; i < 2; i++) {
            int idx = t + i * 256;
            int r = idx >> 4, c4 = (idx & 15) * 4;
            bvs[i] = *(const float4*)&B[(size_t)(kt + r) * N + bn + c4];
        }
    };
    auto stage = [&]() {
        #pragma unroll
        for (int i = 0; i < 4; i++) {
            int idx = t + i * 256;
            int r = idx >> 3, c4 = (idx & 7) * 4;
            // permuted column base: k8*8 + (c4&4 ? 1 : 0), stride 2 per element
            int cb = (c4 >> 3) * 8 + ((c4 >> 2) & 1);
            As[r][cb + 0] = f2tf(avs[i].x);
            As[r][cb + 2] = f2tf(avs[i].y);
            As[r][cb + 4] = f2tf(avs[i].z);
            As[r][cb + 6] = f2tf(avs[i].w);
        }
        #pragma unroll
        for (int i = 0; i < 2; i++) {
            int idx = t + i * 256;
            int r = idx >> 4, c4 = (idx & 15) * 4;
            Bs[r][c4 + 0] = f2tf(bvs[i].x);
            Bs[r][c4 + 1] = f2tf(bvs[i].y);
            Bs[r][c4 + 2] = f2tf(bvs[i].z);
            Bs[r][c4 + 3] = f2tf(bvs[i].w);
        }
    };

    loadA(0); loadB(0);
    stage();
    __syncthreads();

    for (int kt = 0; kt < K; kt += 32) {
        bool nxt = (kt + 32) < K;
        if (nxt) { loadA(kt + 32); loadB(kt + 32); }

        #pragma unroll
        for (int ks = 0; ks < 4; ks++) {
            int k0 = ks * 8;
            unsigned af[2][4], bf[4][2];
            #pragma unroll
            for (int mt = 0; mt < 2; mt++) {
                int rb = warpM * 32 + mt * 16;
                // paired loads: {(row,q),(row,q+4)} at permuted cols k0+2q, k0+2q+1
                uint2 u = *(const uint2*)&As[rb + g][k0 + 2 * q];
                uint2 v = *(const uint2*)&As[rb + g + 8][k0 + 2 * q];
                af[mt][0] = u.x;   // (g,   q)
                af[mt][1] = v.x;   // (g+8, q)
                af[mt][2] = u.y;   // (g,   q+4)
                af[mt][3] = v.y;   // (g+8, q+4)
            }
            #pragma unroll
            for (int nt = 0; nt < 4; nt++) {
                int cb = warpN * 32 + nt * 8;
                bf[nt][0] = Bs[k0 + q][cb + g];
                bf[nt][1] = Bs[k0 + q + 4][cb + g];
            }
            #pragma unroll
            for (int mt = 0; mt < 2; mt++)
                #pragma unroll
                for (int nt = 0; nt < 4; nt++)
                    mma_tf32(acc[mt][nt], af[mt], bf[nt]);
        }
        if (nxt) {
            __syncthreads();
            stage();
            __syncthreads();
        }
    }

    #pragma unroll
    for (int mt = 0; mt < 2; mt++) {
        int r0 = bm + warpM * 32 + mt * 16 + g;
        #pragma unroll
        for (int nt = 0; nt < 4; nt++) {
            int c = bn + warpN * 32 + nt * 8 + q * 2;
            if (r0 < M)
                *(float2*)&C[(size_t)r0 * N + c] = make_float2(acc[mt][nt][0], acc[mt][nt][1]);
            if (r0 + 8 < M)
                *(float2*)&C[(size_t)(r0 + 8) * N + c] = make_float2(acc[mt][nt][2], acc[mt][nt][3]);
        }
    }
}

// ---------------- layer-2 attention dot (main stream; small) ----------------
__global__ void k_attn2(const float* __restrict__ h2res, const float* __restrict__ al,
                        const float* __restrict__ ar, float* __restrict__ el,
                        float* __restrict__ er) {
    int w = (blockIdx.x * blockDim.x + threadIdx.x) >> 5;
    if (w >= NN) return;
    int lane = threadIdx.x & 31;
    const float2* hp = (const float2*)(h2res + (size_t)w * 128);
    float2 h = hp[lane];
    float2 av = ((const float2*)al)[lane];
    float2 rv = ((const float2*)ar)[lane];
    float a = h.x * av.x + h.y * av.y;
    float b = h.x * rv.x + h.y * rv.y;
    #pragma unroll
    for (int o = 16; o; o >>= 1) {
        a += __shfl_xor_sync(FULL, a, o);
        b += __shfl_xor_sync(FULL, b, o);
    }
    if (lane == 0) { el[w] = a; er[w] = b; }
}

// ---------------- layer-1 aggregation: no-shuffle, lane-owns-head, fp32 ----------
__global__ __launch_bounds__(256)
void k_agg1(const int* __restrict__ us, const int* __restrict__ off,
            const float* __restrict__ h1, const float* __restrict__ el,
            const float* __restrict__ er, const float* __restrict__ feats,
            const float* __restrict__ bias, float* __restrict__ x1) {
    int w = (blockIdx.x * blockDim.x + threadIdx.x) >> 5;
    if (w >= NN) return;
    int lane = threadIdx.x & 31;
    int h = lane >> 2;
    int s0 = off[w], s1 = off[w + 1];
    float er_l = er[w * 8 + h];
    float s_l = 0.f;
    float acc[8] = {};

    int i = s0;
    for (; i + 4 <= s1; i += 4) {
        int u0 = us[i], u1 = us[i + 1], u2 = us[i + 2], u3 = us[i + 3];
        float e0 = el[u0 * 8 + h];
        float e1 = el[u1 * 8 + h];
        float e2 = el[u2 * 8 + h];
        float e3 = el[u3 * 8 + h];
        const float4* p0 = (const float4*)(h1 + (size_t)u0 * F1 + lane * 8);
        const float4* p1 = (const float4*)(h1 + (size_t)u1 * F1 + lane * 8);
        const float4* p2 = (const float4*)(h1 + (size_t)u2 * F1 + lane * 8);
        const float4* p3 = (const float4*)(h1 + (size_t)u3 * F1 + lane * 8);
        float4 a0 = p0[0], b0 = p0[1];
        float4 a1 = p1[0], b1 = p1[1];
        float4 a2 = p2[0], b2 = p2[1];
        float4 a3 = p3[0], b3 = p3[1];

        float t0 = e0 + er_l; t0 = t0 > 0.f ? t0 : NEG * t0;
        float t1 = e1 + er_l; t1 = t1 > 0.f ? t1 : NEG * t1;
        float t2 = e2 + er_l; t2 = t2 > 0.f ? t2 : NEG * t2;
        float t3 = e3 + er_l; t3 = t3 > 0.f ? t3 : NEG * t3;
        float w0 = __expf(t0), w1 = __expf(t1), w2 = __expf(t2), w3 = __expf(t3);
        s_l += (w0 + w1) + (w2 + w3);

        acc[0] += a0.x * w0 + a1.x * w1 + a2.x * w2 + a3.x * w3;
        acc[1] += a0.y * w0 + a1.y * w1 + a2.y * w2 + a3.y * w3;
        acc[2] += a0.z * w0 + a1.z * w1 + a2.z * w2 + a3.z * w3;
        acc[3] += a0.w * w0 + a1.w * w1 + a2.w * w2 + a3.w * w3;
        acc[4] += b0.x * w0 + b1.x * w1 + b2.x * w2 + b3.x * w3;
        acc[5] += b0.y * w0 + b1.y * w1 + b2.y * w2 + b3.y * w3;
        acc[6] += b0.z * w0 + b1.z * w1 + b2.z * w2 + b3.z * w3;
        acc[7] += b0.w * w0 + b1.w * w1 + b2.w * w2 + b3.w * w3;
    }
    for (; i < s1; i++) {
        int u = us[i];
        float e = el[u * 8 + h];
        const float4* p = (const float4*)(h1 + (size_t)u * F1 + lane * 8);
        float4 a = p[0], b = p[1];
        float tt = e + er_l;
        tt = tt > 0.f ? tt : NEG * tt;
        float ww = __expf(tt);
        s_l += ww;
        acc[0] += a.x * ww; acc[1] += a.y * ww; acc[2] += a.z * ww; acc[3] += a.w * ww;
        acc[4] += b.x * ww; acc[5] += b.y * ww; acc[6] += b.z * ww; acc[7] += b.w * ww;
    }

    float is = 1.f / s_l;
    int f = lane * 8;
    float4 f0 = *(const float4*)&feats[(size_t)w * FIN + f];
    float4 f1 = *(const float4*)&feats[(size_t)w * FIN + f + 4];
    float4 bA = *(const float4*)&bias[f];
    float4 bB = *(const float4*)&bias[f + 4];
    float o[8];
    o[0] = acc[0] * is + f0.x + bA.x;
    o[1] = acc[1] * is + f0.y + bA.y;
    o[2] = acc[2] * is + f0.z + bA.z;
    o[3] = acc[3] * is + f0.w + bA.w;
    o[4] = acc[4] * is + f1.x + bB.x;
    o[5] = acc[5] * is + f1.y + bB.y;
    o[6] = acc[6] * is + f1.z + bB.z;
    o[7] = acc[7] * is + f1.w + bB.w;
    #pragma unroll
    for (int j = 0; j < 8; j++)
        o[j] = o[j] > 0.f ? o[j] : expm1f(o[j]);
    *(float4*)&x1[(size_t)w * F1 + f]     = make_float4(o[0], o[1], o[2], o[3]);
    *(float4*)&x1[(size_t)w * F1 + f + 4] = make_float4(o[4], o[5], o[6], o[7]);
}

// ---------------- concat [W2 | res_W2] ----------------
__global__ void k_concat(const float* __restrict__ W2, const float* __restrict__ rw,
                         float* __restrict__ Bcat) {
    int i = blockIdx.x * blockDim.x + threadIdx.x;
    if (i < FIN * 128) {
        int k = i >> 7, c = i & 127;
        Bcat[i] = (c < 64) ? W2[k * 64 + c] : rw[k * 64 + (c - 64)];
    }
}

// ---------------- layer-2 aggregation ----------------
__global__ __launch_bounds__(256)
void k_agg2(const int* __restrict__ us, const int* __restrict__ off,
            const float* __restrict__ h2res, const float* __restrict__ el,
            const float* __restrict__ er, const float* __restrict__ bias,
            float* __restrict__ out) {
    int w = (blockIdx.x * blockDim.x + threadIdx.x) >> 5;
    if (w >= NN) return;
    int lane = threadIdx.x & 31;
    int s0 = off[w], s1 = off[w + 1];
    float erv = er[w];
    float s = 0.f;
    float2 acc = make_float2(0.f, 0.f);

    int i = s0;
    for (; i + 4 <= s1; i += 4) {
        int u0 = us[i], u1 = us[i + 1], u2 = us[i + 2], u3 = us[i + 3];
        float e0 = el[u0], e1 = el[u1], e2 = el[u2], e3 = el[u3];
        float2 b0 = *(const float2*)&h2res[(size_t)u0 * 128 + 2 * lane];
        float2 b1 = *(const float2*)&h2res[(size_t)u1 * 128 + 2 * lane];
        float2 b2 = *(const float2*)&h2res[(size_t)u2 * 128 + 2 * lane];
        float2 b3 = *(const float2*)&h2res[(size_t)u3 * 128 + 2 * lane];
        float t0 = e0 + erv; t0 = t0 > 0.f ? t0 : NEG * t0;
        float t1 = e1 + erv; t1 = t1 > 0.f ? t1 : NEG * t1;
        float t2 = e2 + erv; t2 = t2 > 0.f ? t2 : NEG * t2;
        float t3 = e3 + erv; t3 = t3 > 0.f ? t3 : NEG * t3;
        float w0 = __expf(t0), w1 = __expf(t1), w2 = __expf(t2), w3 = __expf(t3);
        s += (w0 + w1) + (w2 + w3);
        acc.x += b0.x * w0 + b1.x * w1 + b2.x * w2 + b3.x * w3;
        acc.y += b0.y * w0 + b1.y * w1 + b2.y * w2 + b3.y * w3;
    }
    for (; i < s1; i++) {
        int u = us[i];
        float tt = el[u] + erv;
        tt = tt > 0.f ? tt : NEG * tt;
        float e = __expf(tt);
        s += e;
        float2 b = *(const float2*)&h2res[(size_t)u * 128 + 2 * lane];
        acc.x += b.x * e;
        acc.y += b.y * e;
    }
    float is = 1.f / s;
    float2 rv = *(const float2*)&h2res[(size_t)w * 128 + 64 + 2 * lane];
    float2 bv = *(const float2*)&bias[2 * lane];
    float2 o;
    o.x = acc.x * is + rv.x + bv.x;
    o.y = acc.y * is + rv.y + bv.y;
    *(float2*)&out[(size_t)w * 64 + 2 * lane] = o;
}

// ---------------- launch ----------------
extern "C" void kernel_launch(void* const* d_in, const int* in_sizes, int n_in,
                              void* d_out, int out_size) {
    const float* feats = (const float*)d_in[0];
    const int*   src   = (const int*)d_in[1];
    const int*   dst   = (const int*)d_in[2];
    const float* W1    = (const float*)d_in[3];
    const float* al1   = (const float*)d_in[4];
    const float* ar1   = (const float*)d_in[5];
    const float* b1    = (const float*)d_in[6];
    const float* W2    = (const float*)d_in[7];
    const float* al2   = (const float*)d_in[8];
    const float* ar2   = (const float*)d_in[9];
    const float* b2    = (const float*)d_in[10];
    const float* rw2   = (const float*)d_in[11];
    float* out = (float*)d_out;
    int E = in_sizes[1];

    float *h1, *el1, *er1, *x1, *h2res, *el2, *er2, *Bcat, *w1l, *w1r;
    int *deg, *off, *us, *bsum;
    cudaGetSymbolAddress((void**)&h1, g_h1);
    cudaGetSymbolAddress((void**)&el1, g_el1);
    cudaGetSymbolAddress((void**)&er1, g_er1);
    cudaGetSymbolAddress((void**)&x1, g_x1);
    cudaGetSymbolAddress((void**)&h2res, g_h2res);
    cudaGetSymbolAddress((void**)&el2, g_el2);
    cudaGetSymbolAddress((void**)&er2, g_er2);
    cudaGetSymbolAddress((void**)&Bcat, g_Bcat);
    cudaGetSymbolAddress((void**)&w1l, g_w1l);
    cudaGetSymbolAddress((void**)&w1r, g_w1r);
    cudaGetSymbolAddress((void**)&deg, g_deg);
    cudaGetSymbolAddress((void**)&off, g_off);
    cudaGetSymbolAddress((void**)&bsum, g_bsum);
    cudaGetSymbolAddress((void**)&us, g_us);

    static cudaStream_t side = nullptr;
    static cudaEvent_t evFork = nullptr, evJoin = nullptr;
    if (!side) {
        cudaStreamCreateWithFlags(&side, cudaStreamNonBlocking);
        cudaEventCreateWithFlags(&evFork, cudaEventDisableTiming);
        cudaEventCreateWithFlags(&evJoin, cudaEventDisableTiming);
    }

    int eb = (E + 255) / 256;
    int wb = (NN * 32 + 255) / 256;

    // fork: CSR build + concat + layer-1 attention dots on side stream
    cudaEventRecord(evFork, 0);
    cudaStreamWaitEvent(side, evFork, 0);
    cudaMemsetAsync(deg, 0, NN * sizeof(int), side);
    k_hist<<<eb, 256, 0, side>>>(dst, E, deg);
    k_scan_blk<<<NB_SCAN, 1024, 0, side>>>(deg, off, bsum, NN);
    k_scan_top<<<1, 32, 0, side>>>(bsum, NB_SCAN);
    k_scan_add<<<NB_SCAN, 1024, 0, side>>>(off, bsum, NN, E);
    cudaMemsetAsync(deg, 0, NN * sizeof(int), side);
    k_scatter<<<eb, 256, 0, side>>>(src, dst, E, off, deg, us);
    k_concat<<<(FIN * 128 + 255) / 256, 256, 0, side>>>(W2, rw2, Bcat);
    k_prevec<<<(FIN * H1N * 32 + 255) / 256, 256, 0, side>>>(W1, al1, ar1, w1l, w1r);
    k_attnpre1<<<wb, 256, 0, side>>>(feats, w1l, w1r, el1, er1);
    cudaEventRecord(evJoin, side);

    // main stream: layer-1 GEMM (concurrent with side chain)
    k_mma_gemm<<<dim3((NN + 127) / 128, F1 / 64), 256>>>(feats, W1, h1, NN, F1, FIN);

    cudaStreamWaitEvent(0, evJoin, 0);
    k_agg1<<<wb, 256>>>(us, off, h1, el1, er1, feats, b1, x1);

    // layer 2
    k_mma_gemm<<<dim3((NN + 127) / 128, 128 / 64), 256>>>(x1, Bcat, h2res, NN, 128, FIN);
    k_attn2<<<wb, 256>>>(h2res, al2, ar2, el2, er2);
    k_agg2<<<wb, 256>>>(us, off, h2res, el2, er2, b2, out);
}

// round 15
// speedup vs baseline: 1.0418x; 1.0418x over previous
#include <cuda_runtime.h>
#include <math.h>

#define NN   50000
#define FIN  256
#define H1N  8
#define F1   256
#define NEG  0.2f
#define EMAX 900000
#define FULL 0xffffffffu
#define NB_SCAN ((NN + 1023) / 1024)

// ---------------- scratch ----------------
__device__ __align__(256) float g_h1[NN * F1];
__device__ __align__(256) float g_el1[NN * H1N];
__device__ __align__(256) float g_er1[NN * H1N];
__device__ __align__(256) float g_x1[NN * F1];
__device__ __align__(256) float g_h2res[NN * 128];   // [h2 (64) | residual (64)]
__device__ __align__(256) float g_el2[NN];
__device__ __align__(256) float g_er2[NN];
__device__ __align__(256) float g_Bcat[FIN * 128];
__device__ __align__(256) float g_w1l[FIN * H1N];    // W1 . al1  [256][8]
__device__ __align__(256) float g_w1r[FIN * H1N];    // W1 . ar1
__device__ int g_deg[NN];
__device__ int g_off[NN + 1];
__device__ int g_bsum[64];
__device__ int g_us[EMAX];

// ---------------- CSR build ----------------
__global__ void k_hist(const int* __restrict__ dst, int E, int* __restrict__ deg) {
    int i = blockIdx.x * blockDim.x + threadIdx.x;
    if (i < E) atomicAdd(&deg[dst[i]], 1);
}

__global__ void k_scan_blk(const int* __restrict__ deg, int* __restrict__ off,
                           int* __restrict__ bsum, int n) {
    __shared__ int wsum[32];
    int tid = threadIdx.x, lane = tid & 31, wid = tid >> 5;
    int i = blockIdx.x * 1024 + tid;
    int v = (i < n) ? deg[i] : 0;
    int x = v;
    #pragma unroll
    for (int o = 1; o < 32; o <<= 1) {
        int y = __shfl_up_sync(FULL, x, o);
        if (lane >= o) x += y;
    }
    if (lane == 31) wsum[wid] = x;
    __syncthreads();
    if (wid == 0) {
        int w = wsum[lane];
        #pragma unroll
        for (int o = 1; o < 32; o <<= 1) {
            int y = __shfl_up_sync(FULL, w, o);
            if (lane >= o) w += y;
        }
        wsum[lane] = w;
    }
    __syncthreads();
    int incl = x + (wid ? wsum[wid - 1] : 0);
    if (i < n) off[i] = incl - v;
    if (tid == 1023) bsum[blockIdx.x] = incl;
}

__global__ void k_scan_top(int* __restrict__ bsum, int nb) {
    if (threadIdx.x == 0) {
        int run = 0;
        for (int b = 0; b < nb; b++) {
            int t = bsum[b];
            bsum[b] = run;
            run += t;
        }
    }
}

__global__ void k_scan_add(int* __restrict__ off, const int* __restrict__ bsum,
                           int n, int E) {
    int i = blockIdx.x * 1024 + threadIdx.x;
    if (i < n) off[i] += bsum[blockIdx.x];
    if (i == 0) off[n] = E;
}

__global__ void k_scatter(const int* __restrict__ src, const int* __restrict__ dst,
                          int E, const int* __restrict__ off, int* __restrict__ cur,
                          int* __restrict__ us) {
    int i = blockIdx.x * blockDim.x + threadIdx.x;
    if (i < E) {
        int d = dst[i];
        int p = off[d] + atomicAdd(&cur[d], 1);
        us[p] = src[i];
    }
}

// ---------------- attn-vector precompose: w1l[f][h] = sum_j W1[f][h*32+j]*al[h][j] ----
__global__ void k_prevec(const float* __restrict__ W1, const float* __restrict__ al,
                         const float* __restrict__ ar, float* __restrict__ w1l,
                         float* __restrict__ w1r) {
    int wid = (blockIdx.x * blockDim.x + threadIdx.x) >> 5;   // 0..2047
    if (wid >= FIN * H1N) return;
    int lane = threadIdx.x & 31;
    int f = wid >> 3, h = wid & 7;
    float p = W1[f * F1 + h * 32 + lane];
    float sl = p * al[h * 32 + lane];
    float sr = p * ar[h * 32 + lane];
    #pragma unroll
    for (int o = 16; o; o >>= 1) {
        sl += __shfl_xor_sync(FULL, sl, o);
        sr += __shfl_xor_sync(FULL, sr, o);
    }
    if (lane == 0) {
        w1l[f * 8 + h] = sl;
        w1r[f * 8 + h] = sr;
    }
}

// ---------------- el1/er1 = feats @ w1l / w1r (warp per node; side stream) --------
__global__ __launch_bounds__(256)
void k_attnpre1(const float* __restrict__ feats, const float* __restrict__ w1l,
                const float* __restrict__ w1r, float* __restrict__ el,
                float* __restrict__ er) {
    int w = (blockIdx.x * blockDim.x + threadIdx.x) >> 5;
    if (w >= NN) return;
    int lane = threadIdx.x & 31;
    const float4* fp = (const float4*)(feats + (size_t)w * FIN + lane * 8);
    float4 v0 = fp[0], v1 = fp[1];
    float fv[8] = {v0.x, v0.y, v0.z, v0.w, v1.x, v1.y, v1.z, v1.w};
    float al[8] = {}, ar[8] = {};
    #pragma unroll
    for (int j = 0; j < 8; j++) {
        int f = lane * 8 + j;
        float4 l0 = *(const float4*)&w1l[f * 8];
        float4 l1 = *(const float4*)&w1l[f * 8 + 4];
        float4 r0 = *(const float4*)&w1r[f * 8];
        float4 r1 = *(const float4*)&w1r[f * 8 + 4];
        float x = fv[j];
        al[0] += x * l0.x; al[1] += x * l0.y; al[2] += x * l0.z; al[3] += x * l0.w;
        al[4] += x * l1.x; al[5] += x * l1.y; al[6] += x * l1.z; al[7] += x * l1.w;
        ar[0] += x * r0.x; ar[1] += x * r0.y; ar[2] += x * r0.z; ar[3] += x * r0.w;
        ar[4] += x * r1.x; ar[5] += x * r1.y; ar[6] += x * r1.z; ar[7] += x * r1.w;
    }
    #pragma unroll
    for (int h = 0; h < 8; h++) {
        #pragma unroll
        for (int o = 16; o; o >>= 1) {
            al[h] += __shfl_xor_sync(FULL, al[h], o);
            ar[h] += __shfl_xor_sync(FULL, ar[h], o);
        }
    }
    #pragma unroll
    for (int h = 0; h < 8; h++) {
        if (lane == h) {
            el[w * 8 + h] = al[h];
            er[w * 8 + h] = ar[h];
        }
    }
}

// ---------------- TF32 tensor-core GEMM (R13/R5-identical — FROZEN) ----------------
__device__ __forceinline__ unsigned f2tf(float x) {
    unsigned u;
    asm("cvt.rna.tf32.f32 %0, %1;" : "=r"(u) : "f"(x));
    return u;
}

__device__ __forceinline__ void mma_tf32(float* d, const unsigned* a, const unsigned* b) {
    asm volatile(
        "mma.sync.aligned.m16n8k8.row.col.f32.tf32.tf32.f32 "
        "{%0,%1,%2,%3}, {%4,%5,%6,%7}, {%8,%9}, {%0,%1,%2,%3};\n"
        : "+f"(d[0]), "+f"(d[1]), "+f"(d[2]), "+f"(d[3])
        : "r"(a[0]), "r"(a[1]), "r"(a[2]), "r"(a[3]), "r"(b[0]), "r"(b[1]));
}

__global__ __launch_bounds__(256)
void k_mma_gemm(const float* __restrict__ A, const float* __restrict__ B,
                float* __restrict__ C, int M, int N, int K) {
    __shared__ unsigned As[128][36];
    __shared__ unsigned Bs[32][72];
    int t = threadIdx.x;
    int lane = t & 31;
    int warp = t >> 5;
    int g = lane >> 2, q = lane & 3;
    int warpM = warp & 3, warpN = warp >> 2;
    int bm = blockIdx.x * 128, bn = blockIdx.y * 64;

    float4 avs[4], bvs[2];
    float acc[2][4][4] = {};

    auto loadA = [&](int kt) {
        #pragma unroll
        for (int i = 0; i < 4; i++) {
            int idx = t + i * 256;
            int r = idx >> 3, c4 = (idx & 7) * 4;
            float4 v = make_float4(0.f, 0.f, 0.f, 0.f);
            if (bm + r < M)
                v = *(const float4*)&A[(size_t)(bm + r) * K + kt + c4];
            avs[i] = v;
        }
    };
    auto loadB = [&](int kt) {
        #pragma unroll
        for (int i = 0; i < 2; i++) {
            int idx = t + i * 256;
            int r = idx >> 4, c4 = (idx & 15) * 4;
            bvs[i] = *(const float4*)&B[(size_t)(kt + r) * N + bn + c4];
        }
    };
    auto stage = [&]() {
        #pragma unroll
        for (int i = 0; i < 4; i++) {
            int idx = t + i * 256;
            int r = idx >> 3, c4 = (idx & 7) * 4;
            As[r][c4 + 0] = f2tf(avs[i].x);
            As[r][c4 + 1] = f2tf(avs[i].y);
            As[r][c4 + 2] = f2tf(avs[i].z);
            As[r][c4 + 3] = f2tf(avs[i].w);
        }
        #pragma unroll
        for (int i = 0; i < 2; i++) {
            int idx = t + i * 256;
            int r = idx >> 4, c4 = (idx & 15) * 4;
            Bs[r][c4 + 0] = f2tf(bvs[i].x);
            Bs[r][c4 + 1] = f2tf(bvs[i].y);
            Bs[r][c4 + 2] = f2tf(bvs[i].z);
            Bs[r][c4 + 3] = f2tf(bvs[i].w);
        }
    };

    loadA(0); loadB(0);
    stage();
    __syncthreads();

    for (int kt = 0; kt < K; kt += 32) {
        bool nxt = (kt + 32) < K;
        if (nxt) { loadA(kt + 32); loadB(kt + 32); }

        #pragma unroll
        for (int ks = 0; ks < 4; ks++) {
            int k0 = ks * 8;
            unsigned af[2][4], bf[4][2];
            #pragma unroll
            for (int mt = 0; mt < 2; mt++) {
                int rb = warpM * 32 + mt * 16;
                af[mt][0] = As[rb + g][k0 + q];
                af[mt][1] = As[rb + g + 8][k0 + q];
                af[mt][2] = As[rb + g][k0 + q + 4];
                af[mt][3] = As[rb + g + 8][k0 + q + 4];
            }
            #pragma unroll
            for (int nt = 0; nt < 4; nt++) {
                int cb = warpN * 32 + nt * 8;
                bf[nt][0] = Bs[k0 + q][cb + g];
                bf[nt][1] = Bs[k0 + q + 4][cb + g];
            }
            #pragma unroll
            for (int mt = 0; mt < 2; mt++)
                #pragma unroll
                for (int nt = 0; nt < 4; nt++)
                    mma_tf32(acc[mt][nt], af[mt], bf[nt]);
        }
        if (nxt) {
            __syncthreads();
            stage();
            __syncthreads();
        }
    }

    #pragma unroll
    for (int mt = 0; mt < 2; mt++) {
        int r0 = bm + warpM * 32 + mt * 16 + g;
        #pragma unroll
        for (int nt = 0; nt < 4; nt++) {
            int c = bn + warpN * 32 + nt * 8 + q * 2;
            if (r0 < M)
                *(float2*)&C[(size_t)r0 * N + c] = make_float2(acc[mt][nt][0], acc[mt][nt][1]);
            if (r0 + 8 < M)
                *(float2*)&C[(size_t)(r0 + 8) * N + c] = make_float2(acc[mt][nt][2], acc[mt][nt][3]);
        }
    }
}

// ---------------- layer-2 attention dot (main stream; small) ----------------
__global__ void k_attn2(const float* __restrict__ h2res, const float* __restrict__ al,
                        const float* __restrict__ ar, float* __restrict__ el,
                        float* __restrict__ er) {
    int w = (blockIdx.x * blockDim.x + threadIdx.x) >> 5;
    if (w >= NN) return;
    int lane = threadIdx.x & 31;
    const float2* hp = (const float2*)(h2res + (size_t)w * 128);
    float2 h = hp[lane];
    float2 av = ((const float2*)al)[lane];
    float2 rv = ((const float2*)ar)[lane];
    float a = h.x * av.x + h.y * av.y;
    float b = h.x * rv.x + h.y * rv.y;
    #pragma unroll
    for (int o = 16; o; o >>= 1) {
        a += __shfl_xor_sync(FULL, a, o);
        b += __shfl_xor_sync(FULL, b, o);
    }
    if (lane == 0) { el[w] = a; er[w] = b; }
}

// ---------------- layer-1 aggregation: no-shuffle, lane-owns-head, fp32 ----------
__global__ __launch_bounds__(256)
void k_agg1(const int* __restrict__ us, const int* __restrict__ off,
            const float* __restrict__ h1, const float* __restrict__ el,
            const float* __restrict__ er, const float* __restrict__ feats,
            const float* __restrict__ bias, float* __restrict__ x1) {
    int w = (blockIdx.x * blockDim.x + threadIdx.x) >> 5;
    if (w >= NN) return;
    int lane = threadIdx.x & 31;
    int h = lane >> 2;
    int s0 = off[w], s1 = off[w + 1];
    float er_l = er[w * 8 + h];
    float s_l = 0.f;
    float acc[8] = {};

    int i = s0;
    for (; i + 4 <= s1; i += 4) {
        int u0 = us[i], u1 = us[i + 1], u2 = us[i + 2], u3 = us[i + 3];
        float e0 = el[u0 * 8 + h];
        float e1 = el[u1 * 8 + h];
        float e2 = el[u2 * 8 + h];
        float e3 = el[u3 * 8 + h];
        const float4* p0 = (const float4*)(h1 + (size_t)u0 * F1 + lane * 8);
        const float4* p1 = (const float4*)(h1 + (size_t)u1 * F1 + lane * 8);
        const float4* p2 = (const float4*)(h1 + (size_t)u2 * F1 + lane * 8);
        const float4* p3 = (const float4*)(h1 + (size_t)u3 * F1 + lane * 8);
        float4 a0 = p0[0], b0 = p0[1];
        float4 a1 = p1[0], b1 = p1[1];
        float4 a2 = p2[0], b2 = p2[1];
        float4 a3 = p3[0], b3 = p3[1];

        float t0 = e0 + er_l; t0 = t0 > 0.f ? t0 : NEG * t0;
        float t1 = e1 + er_l; t1 = t1 > 0.f ? t1 : NEG * t1;
        float t2 = e2 + er_l; t2 = t2 > 0.f ? t2 : NEG * t2;
        float t3 = e3 + er_l; t3 = t3 > 0.f ? t3 : NEG * t3;
        float w0 = __expf(t0), w1 = __expf(t1), w2 = __expf(t2), w3 = __expf(t3);
        s_l += (w0 + w1) + (w2 + w3);

        acc[0] += a0.x * w0 + a1.x * w1 + a2.x * w2 + a3.x * w3;
        acc[1] += a0.y * w0 + a1.y * w1 + a2.y * w2 + a3.y * w3;
        acc[2] += a0.z * w0 + a1.z * w1 + a2.z * w2 + a3.z * w3;
        acc[3] += a0.w * w0 + a1.w * w1 + a2.w * w2 + a3.w * w3;
        acc[4] += b0.x * w0 + b1.x * w1 + b2.x * w2 + b3.x * w3;
        acc[5] += b0.y * w0 + b1.y * w1 + b2.y * w2 + b3.y * w3;
        acc[6] += b0.z * w0 + b1.z * w1 + b2.z * w2 + b3.z * w3;
        acc[7] += b0.w * w0 + b1.w * w1 + b2.w * w2 + b3.w * w3;
    }
    for (; i < s1; i++) {
        int u = us[i];
        float e = el[u * 8 + h];
        const float4* p = (const float4*)(h1 + (size_t)u * F1 + lane * 8);
        float4 a = p[0], b = p[1];
        float tt = e + er_l;
        tt = tt > 0.f ? tt : NEG * tt;
        float ww = __expf(tt);
        s_l += ww;
        acc[0] += a.x * ww; acc[1] += a.y * ww; acc[2] += a.z * ww; acc[3] += a.w * ww;
        acc[4] += b.x * ww; acc[5] += b.y * ww; acc[6] += b.z * ww; acc[7] += b.w * ww;
    }

    float is = 1.f / s_l;
    int f = lane * 8;
    float4 f0 = *(const float4*)&feats[(size_t)w * FIN + f];
    float4 f1 = *(const float4*)&feats[(size_t)w * FIN + f + 4];
    float4 bA = *(const float4*)&bias[f];
    float4 bB = *(const float4*)&bias[f + 4];
    float o[8];
    o[0] = acc[0] * is + f0.x + bA.x;
    o[1] = acc[1] * is + f0.y + bA.y;
    o[2] = acc[2] * is + f0.z + bA.z;
    o[3] = acc[3] * is + f0.w + bA.w;
    o[4] = acc[4] * is + f1.x + bB.x;
    o[5] = acc[5] * is + f1.y + bB.y;
    o[6] = acc[6] * is + f1.z + bB.z;
    o[7] = acc[7] * is + f1.w + bB.w;
    #pragma unroll
    for (int j = 0; j < 8; j++)
        o[j] = o[j] > 0.f ? o[j] : expm1f(o[j]);
    *(float4*)&x1[(size_t)w * F1 + f]     = make_float4(o[0], o[1], o[2], o[3]);
    *(float4*)&x1[(size_t)w * F1 + f + 4] = make_float4(o[4], o[5], o[6], o[7]);
}

// ---------------- concat [W2 | res_W2] ----------------
__global__ void k_concat(const float* __restrict__ W2, const float* __restrict__ rw,
                         float* __restrict__ Bcat) {
    int i = blockIdx.x * blockDim.x + threadIdx.x;
    if (i < FIN * 128) {
        int k = i >> 7, c = i & 127;
        Bcat[i] = (c < 64) ? W2[k * 64 + c] : rw[k * 64 + (c - 64)];
    }
}

// ---------------- layer-2 aggregation ----------------
__global__ __launch_bounds__(256)
void k_agg2(const int* __restrict__ us, const int* __restrict__ off,
            const float* __restrict__ h2res, const float* __restrict__ el,
            const float* __restrict__ er, const float* __restrict__ bias,
            float* __restrict__ out) {
    int w = (blockIdx.x * blockDim.x + threadIdx.x) >> 5;
    if (w >= NN) return;
    int lane = threadIdx.x & 31;
    int s0 = off[w], s1 = off[w + 1];
    float erv = er[w];
    float s = 0.f;
    float2 acc = make_float2(0.f, 0.f);

    int i = s0;
    for (; i + 4 <= s1; i += 4) {
        int u0 = us[i], u1 = us[i + 1], u2 = us[i + 2], u3 = us[i + 3];
        float e0 = el[u0], e1 = el[u1], e2 = el[u2], e3 = el[u3];
        float2 b0 = *(const float2*)&h2res[(size_t)u0 * 128 + 2 * lane];
        float2 b1 = *(const float2*)&h2res[(size_t)u1 * 128 + 2 * lane];
        float2 b2 = *(const float2*)&h2res[(size_t)u2 * 128 + 2 * lane];
        float2 b3 = *(const float2*)&h2res[(size_t)u3 * 128 + 2 * lane];
        float t0 = e0 + erv; t0 = t0 > 0.f ? t0 : NEG * t0;
        float t1 = e1 + erv; t1 = t1 > 0.f ? t1 : NEG * t1;
        float t2 = e2 + erv; t2 = t2 > 0.f ? t2 : NEG * t2;
        float t3 = e3 + erv; t3 = t3 > 0.f ? t3 : NEG * t3;
        float w0 = __expf(t0), w1 = __expf(t1), w2 = __expf(t2), w3 = __expf(t3);
        s += (w0 + w1) + (w2 + w3);
        acc.x += b0.x * w0 + b1.x * w1 + b2.x * w2 + b3.x * w3;
        acc.y += b0.y * w0 + b1.y * w1 + b2.y * w2 + b3.y * w3;
    }
    for (; i < s1; i++) {
        int u = us[i];
        float tt = el[u] + erv;
        tt = tt > 0.f ? tt : NEG * tt;
        float e = __expf(tt);
        s += e;
        float2 b = *(const float2*)&h2res[(size_t)u * 128 + 2 * lane];
        acc.x += b.x * e;
        acc.y += b.y * e;
    }
    float is = 1.f / s;
    float2 rv = *(const float2*)&h2res[(size_t)w * 128 + 64 + 2 * lane];
    float2 bv = *(const float2*)&bias[2 * lane];
    float2 o;
    o.x = acc.x * is + rv.x + bv.x;
    o.y = acc.y * is + rv.y + bv.y;
    *(float2*)&out[(size_t)w * 64 + 2 * lane] = o;
}

// ---------------- launch ----------------
extern "C" void kernel_launch(void* const* d_in, const int* in_sizes, int n_in,
                              void* d_out, int out_size) {
    const float* feats = (const float*)d_in[0];
    const int*   src   = (const int*)d_in[1];
    const int*   dst   = (const int*)d_in[2];
    const float* W1    = (const float*)d_in[3];
    const float* al1   = (const float*)d_in[4];
    const float* ar1   = (const float*)d_in[5];
    const float* b1    = (const float*)d_in[6];
    const float* W2    = (const float*)d_in[7];
    const float* al2   = (const float*)d_in[8];
    const float* ar2   = (const float*)d_in[9];
    const float* b2    = (const float*)d_in[10];
    const float* rw2   = (const float*)d_in[11];
    float* out = (float*)d_out;
    int E = in_sizes[1];

    float *h1, *el1, *er1, *x1, *h2res, *el2, *er2, *Bcat, *w1l, *w1r;
    int *deg, *off, *us, *bsum;
    cudaGetSymbolAddress((void**)&h1, g_h1);
    cudaGetSymbolAddress((void**)&el1, g_el1);
    cudaGetSymbolAddress((void**)&er1, g_er1);
    cudaGetSymbolAddress((void**)&x1, g_x1);
    cudaGetSymbolAddress((void**)&h2res, g_h2res);
    cudaGetSymbolAddress((void**)&el2, g_el2);
    cudaGetSymbolAddress((void**)&er2, g_er2);
    cudaGetSymbolAddress((void**)&Bcat, g_Bcat);
    cudaGetSymbolAddress((void**)&w1l, g_w1l);
    cudaGetSymbolAddress((void**)&w1r, g_w1r);
    cudaGetSymbolAddress((void**)&deg, g_deg);
    cudaGetSymbolAddress((void**)&off, g_off);
    cudaGetSymbolAddress((void**)&bsum, g_bsum);
    cudaGetSymbolAddress((void**)&us, g_us);

    static cudaStream_t side = nullptr;
    static cudaEvent_t evFork = nullptr, evJoin = nullptr;
    if (!side) {
        cudaStreamCreateWithFlags(&side, cudaStreamNonBlocking);
        cudaEventCreateWithFlags(&evFork, cudaEventDisableTiming);
        cudaEventCreateWithFlags(&evJoin, cudaEventDisableTiming);
    }

    int eb = (E + 255) / 256;
    int wb = (NN * 32 + 255) / 256;

    // fork: CSR build + concat + layer-1 attention dots on side stream
    cudaEventRecord(evFork, 0);
    cudaStreamWaitEvent(side, evFork, 0);
    cudaMemsetAsync(deg, 0, NN * sizeof(int), side);
    k_hist<<<eb, 256, 0, side>>>(dst, E, deg);
    k_scan_blk<<<NB_SCAN, 1024, 0, side>>>(deg, off, bsum, NN);
    k_scan_top<<<1, 32, 0, side>>>(bsum, NB_SCAN);
    k_scan_add<<<NB_SCAN, 1024, 0, side>>>(off, bsum, NN, E);
    cudaMemsetAsync(deg, 0, NN * sizeof(int), side);
    k_scatter<<<eb, 256, 0, side>>>(src, dst, E, off, deg, us);
    k_concat<<<(FIN * 128 + 255) / 256, 256, 0, side>>>(W2, rw2, Bcat);
    k_prevec<<<(FIN * H1N * 32 + 255) / 256, 256, 0, side>>>(W1, al1, ar1, w1l, w1r);
    k_attnpre1<<<wb, 256, 0, side>>>(feats, w1l, w1r, el1, er1);
    cudaEventRecord(evJoin, side);

    // main stream: layer-1 GEMM (concurrent with side chain)
    k_mma_gemm<<<dim3((NN + 127) / 128, F1 / 64), 256>>>(feats, W1, h1, NN, F1, FIN);

    cudaStreamWaitEvent(0, evJoin, 0);
    k_agg1<<<wb, 256>>>(us, off, h1, el1, er1, feats, b1, x1);

    // layer 2
    k_mma_gemm<<<dim3((NN + 127) / 128, 128 / 64), 256>>>(x1, Bcat, h2res, NN, 128, FIN);
    k_attn2<<<wb, 256>>>(h2res, al2, ar2, el2, er2);
    k_agg2<<<wb, 256>>>(us, off, h2res, el2, er2, b2, out);
}

// round 16
// speedup vs baseline: 1.7192x; 1.6502x over previous
#include <cuda_runtime.h>
#include <math.h>

#define NN   50000
#define FIN  256
#define H1N  8
#define F1   256
#define NEG  0.2f
#define EMAX 900000
#define FULL 0xffffffffu
#define NB_SCAN ((NN + 1023) / 1024)

// ---------------- scratch ----------------
__device__ __align__(256) float g_h1[NN * F1];
__device__ __align__(256) float g_elr1[NN * 64];     // [el(8) | er(8) | pad(48)] per node
__device__ __align__(256) float g_x1[NN * F1];
__device__ __align__(256) float g_h2res[NN * 128];   // [h2 (64) | residual (64)]
__device__ __align__(256) float g_el2[NN];
__device__ __align__(256) float g_er2[NN];
__device__ __align__(256) float g_Bcat[FIN * 128];
__device__ __align__(256) float g_W1a[FIN * 64];     // [W1.al1 (8) | W1.ar1 (8) | 0 (48)]; cols 16-63 stay zero
__device__ int g_deg[NN];
__device__ int g_off[NN + 1];
__device__ int g_bsum[64];
__device__ int g_us[EMAX];

// ---------------- CSR build ----------------
__global__ void k_hist(const int* __restrict__ dst, int E, int* __restrict__ deg) {
    int i = blockIdx.x * blockDim.x + threadIdx.x;
    if (i < E) atomicAdd(&deg[dst[i]], 1);
}

__global__ void k_scan_blk(const int* __restrict__ deg, int* __restrict__ off,
                           int* __restrict__ bsum, int n) {
    __shared__ int wsum[32];
    int tid = threadIdx.x, lane = tid & 31, wid = tid >> 5;
    int i = blockIdx.x * 1024 + tid;
    int v = (i < n) ? deg[i] : 0;
    int x = v;
    #pragma unroll
    for (int o = 1; o < 32; o <<= 1) {
        int y = __shfl_up_sync(FULL, x, o);
        if (lane >= o) x += y;
    }
    if (lane == 31) wsum[wid] = x;
    __syncthreads();
    if (wid == 0) {
        int w = wsum[lane];
        #pragma unroll
        for (int o = 1; o < 32; o <<= 1) {
            int y = __shfl_up_sync(FULL, w, o);
            if (lane >= o) w += y;
        }
        wsum[lane] = w;
    }
    __syncthreads();
    int incl = x + (wid ? wsum[wid - 1] : 0);
    if (i < n) off[i] = incl - v;
    if (tid == 1023) bsum[blockIdx.x] = incl;
}

__global__ void k_scan_top(int* __restrict__ bsum, int nb) {
    if (threadIdx.x == 0) {
        int run = 0;
        for (int b = 0; b < nb; b++) {
            int t = bsum[b];
            bsum[b] = run;
            run += t;
        }
    }
}

__global__ void k_scan_add(int* __restrict__ off, const int* __restrict__ bsum,
                           int n, int E) {
    int i = blockIdx.x * 1024 + threadIdx.x;
    if (i < n) off[i] += bsum[blockIdx.x];
    if (i == 0) off[n] = E;
}

__global__ void k_scatter(const int* __restrict__ src, const int* __restrict__ dst,
                          int E, const int* __restrict__ off, int* __restrict__ cur,
                          int* __restrict__ us) {
    int i = blockIdx.x * blockDim.x + threadIdx.x;
    if (i < E) {
        int d = dst[i];
        int p = off[d] + atomicAdd(&cur[d], 1);
        us[p] = src[i];
    }
}

// ---------------- attn-vector precompose into W1a ----------------
// W1a[f][h] = sum_j W1[f][h*32+j]*al[h][j];  W1a[f][8+h] = same with ar.
__global__ void k_prevec(const float* __restrict__ W1, const float* __restrict__ al,
                         const float* __restrict__ ar, float* __restrict__ W1a) {
    int wid = (blockIdx.x * blockDim.x + threadIdx.x) >> 5;   // 0..2047
    if (wid >= FIN * H1N) return;
    int lane = threadIdx.x & 31;
    int f = wid >> 3, h = wid & 7;
    float p = W1[f * F1 + h * 32 + lane];
    float sl = p * al[h * 32 + lane];
    float sr = p * ar[h * 32 + lane];
    #pragma unroll
    for (int o = 16; o; o >>= 1) {
        sl += __shfl_xor_sync(FULL, sl, o);
        sr += __shfl_xor_sync(FULL, sr, o);
    }
    if (lane == 0) {
        W1a[f * 64 + h]     = sl;
        W1a[f * 64 + 8 + h] = sr;
    }
}

// ---------------- TF32 tensor-core GEMM (R13/R5-identical — FROZEN) ----------------
__device__ __forceinline__ unsigned f2tf(float x) {
    unsigned u;
    asm("cvt.rna.tf32.f32 %0, %1;" : "=r"(u) : "f"(x));
    return u;
}

__device__ __forceinline__ void mma_tf32(float* d, const unsigned* a, const unsigned* b) {
    asm volatile(
        "mma.sync.aligned.m16n8k8.row.col.f32.tf32.tf32.f32 "
        "{%0,%1,%2,%3}, {%4,%5,%6,%7}, {%8,%9}, {%0,%1,%2,%3};\n"
        : "+f"(d[0]), "+f"(d[1]), "+f"(d[2]), "+f"(d[3])
        : "r"(a[0]), "r"(a[1]), "r"(a[2]), "r"(a[3]), "r"(b[0]), "r"(b[1]));
}

__global__ __launch_bounds__(256)
void k_mma_gemm(const float* __restrict__ A, const float* __restrict__ B,
                float* __restrict__ C, int M, int N, int K) {
    __shared__ unsigned As[128][36];
    __shared__ unsigned Bs[32][72];
    int t = threadIdx.x;
    int lane = t & 31;
    int warp = t >> 5;
    int g = lane >> 2, q = lane & 3;
    int warpM = warp & 3, warpN = warp >> 2;
    int bm = blockIdx.x * 128, bn = blockIdx.y * 64;

    float4 avs[4], bvs[2];
    float acc[2][4][4] = {};

    auto loadA = [&](int kt) {
        #pragma unroll
        for (int i = 0; i < 4; i++) {
            int idx = t + i * 256;
            int r = idx >> 3, c4 = (idx & 7) * 4;
            float4 v = make_float4(0.f, 0.f, 0.f, 0.f);
            if (bm + r < M)
                v = *(const float4*)&A[(size_t)(bm + r) * K + kt + c4];
            avs[i] = v;
        }
    };
    auto loadB = [&](int kt) {
        #pragma unroll
        for (int i = 0; i < 2; i++) {
            int idx = t + i * 256;
            int r = idx >> 4, c4 = (idx & 15) * 4;
            bvs[i] = *(const float4*)&B[(size_t)(kt + r) * N + bn + c4];
        }
    };
    auto stage = [&]() {
        #pragma unroll
        for (int i = 0; i < 4; i++) {
            int idx = t + i * 256;
            int r = idx >> 3, c4 = (idx & 7) * 4;
            As[r][c4 + 0] = f2tf(avs[i].x);
            As[r][c4 + 1] = f2tf(avs[i].y);
            As[r][c4 + 2] = f2tf(avs[i].z);
            As[r][c4 + 3] = f2tf(avs[i].w);
        }
        #pragma unroll
        for (int i = 0; i < 2; i++) {
            int idx = t + i * 256;
            int r = idx >> 4, c4 = (idx & 15) * 4;
            Bs[r][c4 + 0] = f2tf(bvs[i].x);
            Bs[r][c4 + 1] = f2tf(bvs[i].y);
            Bs[r][c4 + 2] = f2tf(bvs[i].z);
            Bs[r][c4 + 3] = f2tf(bvs[i].w);
        }
    };

    loadA(0); loadB(0);
    stage();
    __syncthreads();

    for (int kt = 0; kt < K; kt += 32) {
        bool nxt = (kt + 32) < K;
        if (nxt) { loadA(kt + 32); loadB(kt + 32); }

        #pragma unroll
        for (int ks = 0; ks < 4; ks++) {
            int k0 = ks * 8;
            unsigned af[2][4], bf[4][2];
            #pragma unroll
            for (int mt = 0; mt < 2; mt++) {
                int rb = warpM * 32 + mt * 16;
                af[mt][0] = As[rb + g][k0 + q];
                af[mt][1] = As[rb + g + 8][k0 + q];
                af[mt][2] = As[rb + g][k0 + q + 4];
                af[mt][3] = As[rb + g + 8][k0 + q + 4];
            }
            #pragma unroll
            for (int nt = 0; nt < 4; nt++) {
                int cb = warpN * 32 + nt * 8;
                bf[nt][0] = Bs[k0 + q][cb + g];
                bf[nt][1] = Bs[k0 + q + 4][cb + g];
            }
            #pragma unroll
            for (int mt = 0; mt < 2; mt++)
                #pragma unroll
                for (int nt = 0; nt < 4; nt++)
                    mma_tf32(acc[mt][nt], af[mt], bf[nt]);
        }
        if (nxt) {
            __syncthreads();
            stage();
            __syncthreads();
        }
    }

    #pragma unroll
    for (int mt = 0; mt < 2; mt++) {
        int r0 = bm + warpM * 32 + mt * 16 + g;
        #pragma unroll
        for (int nt = 0; nt < 4; nt++) {
            int c = bn + warpN * 32 + nt * 8 + q * 2;
            if (r0 < M)
                *(float2*)&C[(size_t)r0 * N + c] = make_float2(acc[mt][nt][0], acc[mt][nt][1]);
            if (r0 + 8 < M)
                *(float2*)&C[(size_t)(r0 + 8) * N + c] = make_float2(acc[mt][nt][2], acc[mt][nt][3]);
        }
    }
}

// ---------------- layer-2 attention dot ----------------
__global__ void k_attn2(const float* __restrict__ h2res, const float* __restrict__ al,
                        const float* __restrict__ ar, float* __restrict__ el,
                        float* __restrict__ er) {
    int w = (blockIdx.x * blockDim.x + threadIdx.x) >> 5;
    if (w >= NN) return;
    int lane = threadIdx.x & 31;
    const float2* hp = (const float2*)(h2res + (size_t)w * 128);
    float2 h = hp[lane];
    float2 av = ((const float2*)al)[lane];
    float2 rv = ((const float2*)ar)[lane];
    float a = h.x * av.x + h.y * av.y;
    float b = h.x * rv.x + h.y * rv.y;
    #pragma unroll
    for (int o = 16; o; o >>= 1) {
        a += __shfl_xor_sync(FULL, a, o);
        b += __shfl_xor_sync(FULL, b, o);
    }
    if (lane == 0) { el[w] = a; er[w] = b; }
}

// ---------------- layer-1 aggregation: no-shuffle, lane-owns-head, fp32 ----------
// el/er packed in elr[node*64]: el at +h, er at +8+h.
__global__ __launch_bounds__(256)
void k_agg1(const int* __restrict__ us, const int* __restrict__ off,
            const float* __restrict__ h1, const float* __restrict__ elr,
            const float* __restrict__ feats, const float* __restrict__ bias,
            float* __restrict__ x1) {
    int w = (blockIdx.x * blockDim.x + threadIdx.x) >> 5;
    if (w >= NN) return;
    int lane = threadIdx.x & 31;
    int h = lane >> 2;
    int s0 = off[w], s1 = off[w + 1];
    float er_l = elr[(size_t)w * 64 + 8 + h];
    float s_l = 0.f;
    float acc[8] = {};

    int i = s0;
    for (; i + 4 <= s1; i += 4) {
        int u0 = us[i], u1 = us[i + 1], u2 = us[i + 2], u3 = us[i + 3];
        float e0 = elr[(size_t)u0 * 64 + h];
        float e1 = elr[(size_t)u1 * 64 + h];
        float e2 = elr[(size_t)u2 * 64 + h];
        float e3 = elr[(size_t)u3 * 64 + h];
        const float4* p0 = (const float4*)(h1 + (size_t)u0 * F1 + lane * 8);
        const float4* p1 = (const float4*)(h1 + (size_t)u1 * F1 + lane * 8);
        const float4* p2 = (const float4*)(h1 + (size_t)u2 * F1 + lane * 8);
        const float4* p3 = (const float4*)(h1 + (size_t)u3 * F1 + lane * 8);
        float4 a0 = p0[0], b0 = p0[1];
        float4 a1 = p1[0], b1 = p1[1];
        float4 a2 = p2[0], b2 = p2[1];
        float4 a3 = p3[0], b3 = p3[1];

        float t0 = e0 + er_l; t0 = t0 > 0.f ? t0 : NEG * t0;
        float t1 = e1 + er_l; t1 = t1 > 0.f ? t1 : NEG * t1;
        float t2 = e2 + er_l; t2 = t2 > 0.f ? t2 : NEG * t2;
        float t3 = e3 + er_l; t3 = t3 > 0.f ? t3 : NEG * t3;
        float w0 = __expf(t0), w1 = __expf(t1), w2 = __expf(t2), w3 = __expf(t3);
        s_l += (w0 + w1) + (w2 + w3);

        acc[0] += a0.x * w0 + a1.x * w1 + a2.x * w2 + a3.x * w3;
        acc[1] += a0.y * w0 + a1.y * w1 + a2.y * w2 + a3.y * w3;
        acc[2] += a0.z * w0 + a1.z * w1 + a2.z * w2 + a3.z * w3;
        acc[3] += a0.w * w0 + a1.w * w1 + a2.w * w2 + a3.w * w3;
        acc[4] += b0.x * w0 + b1.x * w1 + b2.x * w2 + b3.x * w3;
        acc[5] += b0.y * w0 + b1.y * w1 + b2.y * w2 + b3.y * w3;
        acc[6] += b0.z * w0 + b1.z * w1 + b2.z * w2 + b3.z * w3;
        acc[7] += b0.w * w0 + b1.w * w1 + b2.w * w2 + b3.w * w3;
    }
    for (; i < s1; i++) {
        int u = us[i];
        float e = elr[(size_t)u * 64 + h];
        const float4* p = (const float4*)(h1 + (size_t)u * F1 + lane * 8);
        float4 a = p[0], b = p[1];
        float tt = e + er_l;
        tt = tt > 0.f ? tt : NEG * tt;
        float ww = __expf(tt);
        s_l += ww;
        acc[0] += a.x * ww; acc[1] += a.y * ww; acc[2] += a.z * ww; acc[3] += a.w * ww;
        acc[4] += b.x * ww; acc[5] += b.y * ww; acc[6] += b.z * ww; acc[7] += b.w * ww;
    }

    float is = 1.f / s_l;
    int f = lane * 8;
    float4 f0 = *(const float4*)&feats[(size_t)w * FIN + f];
    float4 f1 = *(const float4*)&feats[(size_t)w * FIN + f + 4];
    float4 bA = *(const float4*)&bias[f];
    float4 bB = *(const float4*)&bias[f + 4];
    float o[8];
    o[0] = acc[0] * is + f0.x + bA.x;
    o[1] = acc[1] * is + f0.y + bA.y;
    o[2] = acc[2] * is + f0.z + bA.z;
    o[3] = acc[3] * is + f0.w + bA.w;
    o[4] = acc[4] * is + f1.x + bB.x;
    o[5] = acc[5] * is + f1.y + bB.y;
    o[6] = acc[6] * is + f1.z + bB.z;
    o[7] = acc[7] * is + f1.w + bB.w;
    #pragma unroll
    for (int j = 0; j < 8; j++)
        o[j] = o[j] > 0.f ? o[j] : expm1f(o[j]);
    *(float4*)&x1[(size_t)w * F1 + f]     = make_float4(o[0], o[1], o[2], o[3]);
    *(float4*)&x1[(size_t)w * F1 + f + 4] = make_float4(o[4], o[5], o[6], o[7]);
}

// ---------------- concat [W2 | res_W2] ----------------
__global__ void k_concat(const float* __restrict__ W2, const float* __restrict__ rw,
                         float* __restrict__ Bcat) {
    int i = blockIdx.x * blockDim.x + threadIdx.x;
    if (i < FIN * 128) {
        int k = i >> 7, c = i & 127;
        Bcat[i] = (c < 64) ? W2[k * 64 + c] : rw[k * 64 + (c - 64)];
    }
}

// ---------------- layer-2 aggregation ----------------
__global__ __launch_bounds__(256)
void k_agg2(const int* __restrict__ us, const int* __restrict__ off,
            const float* __restrict__ h2res, const float* __restrict__ el,
            const float* __restrict__ er, const float* __restrict__ bias,
            float* __restrict__ out) {
    int w = (blockIdx.x * blockDim.x + threadIdx.x) >> 5;
    if (w >= NN) return;
    int lane = threadIdx.x & 31;
    int s0 = off[w], s1 = off[w + 1];
    float erv = er[w];
    float s = 0.f;
    float2 acc = make_float2(0.f, 0.f);

    int i = s0;
    for (; i + 4 <= s1; i += 4) {
        int u0 = us[i], u1 = us[i + 1], u2 = us[i + 2], u3 = us[i + 3];
        float e0 = el[u0], e1 = el[u1], e2 = el[u2], e3 = el[u3];
        float2 b0 = *(const float2*)&h2res[(size_t)u0 * 128 + 2 * lane];
        float2 b1 = *(const float2*)&h2res[(size_t)u1 * 128 + 2 * lane];
        float2 b2 = *(const float2*)&h2res[(size_t)u2 * 128 + 2 * lane];
        float2 b3 = *(const float2*)&h2res[(size_t)u3 * 128 + 2 * lane];
        float t0 = e0 + erv; t0 = t0 > 0.f ? t0 : NEG * t0;
        float t1 = e1 + erv; t1 = t1 > 0.f ? t1 : NEG * t1;
        float t2 = e2 + erv; t2 = t2 > 0.f ? t2 : NEG * t2;
        float t3 = e3 + erv; t3 = t3 > 0.f ? t3 : NEG * t3;
        float w0 = __expf(t0), w1 = __expf(t1), w2 = __expf(t2), w3 = __expf(t3);
        s += (w0 + w1) + (w2 + w3);
        acc.x += b0.x * w0 + b1.x * w1 + b2.x * w2 + b3.x * w3;
        acc.y += b0.y * w0 + b1.y * w1 + b2.y * w2 + b3.y * w3;
    }
    for (; i < s1; i++) {
        int u = us[i];
        float tt = el[u] + erv;
        tt = tt > 0.f ? tt : NEG * tt;
        float e = __expf(tt);
        s += e;
        float2 b = *(const float2*)&h2res[(size_t)u * 128 + 2 * lane];
        acc.x += b.x * e;
        acc.y += b.y * e;
    }
    float is = 1.f / s;
    float2 rv = *(const float2*)&h2res[(size_t)w * 128 + 64 + 2 * lane];
    float2 bv = *(const float2*)&bias[2 * lane];
    float2 o;
    o.x = acc.x * is + rv.x + bv.x;
    o.y = acc.y * is + rv.y + bv.y;
    *(float2*)&out[(size_t)w * 64 + 2 * lane] = o;
}

// ---------------- launch ----------------
extern "C" void kernel_launch(void* const* d_in, const int* in_sizes, int n_in,
                              void* d_out, int out_size) {
    const float* feats = (const float*)d_in[0];
    const int*   src   = (const int*)d_in[1];
    const int*   dst   = (const int*)d_in[2];
    const float* W1    = (const float*)d_in[3];
    const float* al1   = (const float*)d_in[4];
    const float* ar1   = (const float*)d_in[5];
    const float* b1    = (const float*)d_in[6];
    const float* W2    = (const float*)d_in[7];
    const float* al2   = (const float*)d_in[8];
    const float* ar2   = (const float*)d_in[9];
    const float* b2    = (const float*)d_in[10];
    const float* rw2   = (const float*)d_in[11];
    float* out = (float*)d_out;
    int E = in_sizes[1];

    float *h1, *elr1, *x1, *h2res, *el2, *er2, *Bcat, *W1a;
    int *deg, *off, *us, *bsum;
    cudaGetSymbolAddress((void**)&h1, g_h1);
    cudaGetSymbolAddress((void**)&elr1, g_elr1);
    cudaGetSymbolAddress((void**)&x1, g_x1);
    cudaGetSymbolAddress((void**)&h2res, g_h2res);
    cudaGetSymbolAddress((void**)&el2, g_el2);
    cudaGetSymbolAddress((void**)&er2, g_er2);
    cudaGetSymbolAddress((void**)&Bcat, g_Bcat);
    cudaGetSymbolAddress((void**)&W1a, g_W1a);
    cudaGetSymbolAddress((void**)&deg, g_deg);
    cudaGetSymbolAddress((void**)&off, g_off);
    cudaGetSymbolAddress((void**)&bsum, g_bsum);
    cudaGetSymbolAddress((void**)&us, g_us);

    static cudaStream_t side = nullptr;
    static cudaEvent_t evFork = nullptr, evJoin = nullptr;
    if (!side) {
        cudaStreamCreateWithFlags(&side, cudaStreamNonBlocking);
        cudaEventCreateWithFlags(&evFork, cudaEventDisableTiming);
        cudaEventCreateWithFlags(&evJoin, cudaEventDisableTiming);
    }

    int eb = (E + 255) / 256;
    int wb = (NN * 32 + 255) / 256;

    // fork: CSR build + concat + layer-1 attention scores on side stream.
    // W1a cols 16-63 are static-zero and never written; k_prevec refreshes 0-15.
    cudaEventRecord(evFork, 0);
    cudaStreamWaitEvent(side, evFork, 0);
    cudaMemsetAsync(deg, 0, NN * sizeof(int), side);
    k_hist<<<eb, 256, 0, side>>>(dst, E, deg);
    k_scan_blk<<<NB_SCAN, 1024, 0, side>>>(deg, off, bsum, NN);
    k_scan_top<<<1, 32, 0, side>>>(bsum, NB_SCAN);
    k_scan_add<<<NB_SCAN, 1024, 0, side>>>(off, bsum, NN, E);
    cudaMemsetAsync(deg, 0, NN * sizeof(int), side);
    k_scatter<<<eb, 256, 0, side>>>(src, dst, E, off, deg, us);
    k_concat<<<(FIN * 128 + 255) / 256, 256, 0, side>>>(W2, rw2, Bcat);
    k_prevec<<<(FIN * H1N * 32 + 255) / 256, 256, 0, side>>>(W1, al1, ar1, W1a);
    // elr1 = feats @ W1a  (el cols 0-7, er cols 8-15) — dense GEMM, coalesced
    k_mma_gemm<<<dim3((NN + 127) / 128, 1), 256, 0, side>>>(feats, W1a, elr1, NN, 64, FIN);
    cudaEventRecord(evJoin, side);

    // main stream: layer-1 GEMM (concurrent with side chain)
    k_mma_gemm<<<dim3((NN + 127) / 128, F1 / 64), 256>>>(feats, W1, h1, NN, F1, FIN);

    cudaStreamWaitEvent(0, evJoin, 0);
    k_agg1<<<wb, 256>>>(us, off, h1, elr1, feats, b1, x1);

    // layer 2
    k_mma_gemm<<<dim3((NN + 127) / 128, 128 / 64), 256>>>(x1, Bcat, h2res, NN, 128, FIN);
    k_attn2<<<wb, 256>>>(h2res, al2, ar2, el2, er2);
    k_agg2<<<wb, 256>>>(us, off, h2res, el2, er2, b2, out);
}